// round 12
// baseline (speedup 1.0000x reference)
#include <cuda_runtime.h>
#include <cuda_bf16.h>
#include <cstdint>

#define HH 300
#define G4 1200
#define NTW 192                 // 6 warps: one weight tile each

// SMEM offsets (bytes)
#define SM_A    0               // 6 tiles x 19456 = 116736
#define SM_HSTH 116736          // staging hi: 16 rows x 608 = 9728
#define SM_HSTL 126464          // staging lo: 9728
#define SM_C    136192          // c-state: 24 units x 128 rows x f32 = 12288
#define SM_TOT  148480

__device__ __align__(256) float Wt2_g[600 * G4];   // step0 weights [k][u*4+g]
__device__ __align__(256) float Wc2_g[HH * G4];    // folded [k][u*4+g]
__device__ __align__(256) float bias2_g[G4];
__device__ __align__(256) float biasf_g[G4];
__device__ __align__(256) __nv_bfloat16 AT_g[96 * 9728];  // [tile][kt][hl][r16][k16]
__device__ float c1_g[1024 * HH];
__device__ float hP0_g[1024 * HH];
__device__ float hP1_g[1024 * HH];
__device__ unsigned bar_cnt_g;

__device__ __forceinline__ uint32_t smem_u32(const void* p) {
    uint32_t a;
    asm("{ .reg .u64 t; cvta.to.shared.u64 t, %1; cvt.u32.u64 %0, t; }" : "=r"(a) : "l"(p));
    return a;
}
__device__ __forceinline__ float sigf(float x) {
    return __fdividef(1.0f, 1.0f + __expf(-x));
}
__device__ __forceinline__ float tanhf_fast(float x) {
    return 1.0f - 2.0f * __fdividef(1.0f, __expf(2.0f * x) + 1.0f);
}
__device__ __forceinline__ void ldsm4(uint32_t* a, uint32_t addr) {
    asm volatile("ldmatrix.sync.aligned.m8n8.x4.shared.b16 {%0,%1,%2,%3},[%4];"
                 : "=r"(a[0]), "=r"(a[1]), "=r"(a[2]), "=r"(a[3]) : "r"(addr));
}
__device__ __forceinline__ void mma16(float* d, const uint32_t* a, uint32_t b0, uint32_t b1) {
    asm volatile(
        "mma.sync.aligned.m16n8k16.row.col.f32.bf16.bf16.f32 "
        "{%0,%1,%2,%3},{%4,%5,%6,%7},{%8,%9},{%0,%1,%2,%3};"
        : "+f"(d[0]), "+f"(d[1]), "+f"(d[2]), "+f"(d[3])
        : "r"(a[0]), "r"(a[1]), "r"(a[2]), "r"(a[3]), "r"(b0), "r"(b1));
}

// ---------------- prep (identical to passing R11) ----------------
__global__ void prep_basic(const float* W_ih, const float* W_hh, const float* b_ih,
                           const float* b_hh) {
    int idx = blockIdx.x * blockDim.x + threadIdx.x;
    if (idx < 600 * G4) {
        int k = idx / G4, col = idx % G4, u = col >> 2, g = col & 3, n = u + HH * g;
        Wt2_g[idx] = (k < HH) ? W_ih[n * HH + k] : W_hh[n * HH + (k - HH)];
    }
    int i3 = idx - 600 * G4;
    if (i3 >= 0 && i3 < G4) {
        int u = i3 >> 2, g = i3 & 3;
        bias2_g[i3] = b_ih[u + HH * g] + b_hh[u + HH * g];
    }
}
__global__ void prep_fold(const float* W_ih, const float* W_hh, const float* W_out) {
    __shared__ float sw[HH][20];
    int tid = threadIdx.x, kk = tid % 20, c = tid / 20;
    int k = blockIdx.y * 20 + kk, col = blockIdx.x * 16 + c;
    int u = col >> 2, g = col & 3, n = u + HH * g;
    for (int i = tid; i < HH * 20; i += 320)
        sw[i / 20][i % 20] = W_out[(i / 20) * HH + blockIdx.y * 20 + (i % 20)];
    __syncthreads();
    float acc = W_hh[n * HH + k];
    const float* wr = &W_ih[n * HH];
    #pragma unroll 4
    for (int j = 0; j < HH; ++j) acc = fmaf(__ldg(&wr[j]), sw[j][kk], acc);
    Wc2_g[k * G4 + col] = acc;
}
__global__ void prep_biasf(const float* W_ih, const float* b_ih, const float* b_hh,
                           const float* b_out) {
    int col = blockIdx.x * blockDim.x + threadIdx.x;
    if (col >= G4) return;
    int u = col >> 2, g = col & 3, n = u + HH * g;
    float acc = b_ih[n] + b_hh[n];
    const float* wr = &W_ih[n * HH];
    #pragma unroll 4
    for (int j = 0; j < HH; ++j) acc = fmaf(__ldg(&wr[j]), __ldg(&b_out[j]), acc);
    biasf_g[col] = acc;
}
__global__ void prep_pack(const float* W_out) {
    int idx = blockIdx.x * blockDim.x + threadIdx.x;
    if (idx >= 96 * 9728) return;
    int t = idx / 9728, e = idx % 9728;
    int kt = e >> 9, e2 = e & 511, half = e2 >> 8, e3 = e2 & 255, r = e3 >> 4, k16 = e3 & 15;
    int k = kt * 16 + k16;
    float v = 0.f;
    if (t < 75) {
        int c = 16 * t + r;
        if (k < HH) v = Wc2_g[k * G4 + c];
    } else if (t < 94) {
        int n = 16 * (t - 75) + r;
        if (n < HH && k < HH) v = W_out[n * HH + k];
    }
    __nv_bfloat16 hi = __float2bfloat16(v);
    AT_g[idx] = half ? __float2bfloat16(v - __bfloat162float(hi)) : hi;
}
__global__ void reset_bar() { bar_cnt_g = 0u; }

// ---------------- step 0 (K=600, exact fp32) -> h1 (hP1), c1 ----------------
__global__ void __launch_bounds__(320, 1)
step0(const float* h0, const float* c0, const float* start, int B) {
    __shared__ float xh[600 * 8];
    int tid = threadIdx.x, r0 = blockIdx.x * 8;
    for (int idx = tid; idx < HH * 8; idx += 320) {
        int u = idx >> 3, b = idx & 7;
        xh[u * 8 + b] = start[(size_t)(r0 + b) * HH + u];
        xh[(HH + u) * 8 + b] = h0[(size_t)(r0 + b) * HH + u];
    }
    __syncthreads();
    if (tid < HH) {
        float a0[8], a1[8], a2[8], a3[8];
        float4 bb = *(const float4*)&bias2_g[tid * 4];
        #pragma unroll
        for (int b = 0; b < 8; ++b) { a0[b] = bb.x; a1[b] = bb.y; a2[b] = bb.z; a3[b] = bb.w; }
        for (int k = 0; k < 600; ++k) {
            float4 wv = *(const float4*)&Wt2_g[k * G4 + tid * 4];
            #pragma unroll
            for (int b = 0; b < 8; ++b) {
                float xv = xh[k * 8 + b];
                a0[b] = fmaf(xv, wv.x, a0[b]); a1[b] = fmaf(xv, wv.y, a1[b]);
                a2[b] = fmaf(xv, wv.z, a2[b]); a3[b] = fmaf(xv, wv.w, a3[b]);
            }
        }
        #pragma unroll
        for (int b = 0; b < 8; ++b) {
            float iv = sigf(a0[b]), fv = sigf(a1[b]);
            float gv = tanhf_fast(a2[b]), ov = sigf(a3[b]);
            float cc = fmaf(fv, c0[(size_t)(r0 + b) * HH + tid], iv * gv);
            hP1_g[(size_t)(r0 + b) * HH + tid] = ov * tanhf_fast(cc);
            c1_g[(size_t)(r0 + b) * HH + tid] = cc;
        }
    }
}

// ---------------- persistent HMMA kernel ----------------
// 128 CTAs = 8 sets x 16 ranks. rank -> 6 resident tiles; set -> 128 batch rows.
// Per iteration: 8 passes of 16 rows (two 8-row chunks, 6 independent MMA chains).
__global__ void __launch_bounds__(NTW, 1)
lstm_hmma(const float* __restrict__ b_out, float* __restrict__ out, int B, int steps) {
    extern __shared__ char sm[];
    const uint32_t sb = smem_u32(sm);
    const int tid = threadIdx.x, wid = tid >> 5, lane = tid & 31;
    const int rank = blockIdx.x & 15;
    const int set = blockIdx.x >> 4;
    const int r0set = set * 128;
    const unsigned NB = gridDim.x;
    float* c_sm = (float*)(sm + SM_C);

    // resident A tiles
    {
        const uint4* src = (const uint4*)(AT_g + (size_t)rank * 6 * 9728);
        uint4* dst = (uint4*)sm;
        for (int i = tid; i < 7296; i += NTW) dst[i] = src[i];
    }
    // zero staging (pad units 300-303 never rewritten -> stay 0)
    for (int i = tid; i < 19456 / 4; i += NTW) ((uint32_t*)(sm + SM_HSTH))[i] = 0;
    // c-state init
    for (int i = tid; i < 24 * 128; i += NTW) {
        int ul = i >> 7, ns = i & 127, u = rank * 24 + ul;
        if (u < HH) c_sm[i] = c1_g[(size_t)(r0set + ns) * HH + u];
    }
    __syncthreads();

    const int T = rank * 6 + wid;
    const bool isG = (T < 75), isO = (T >= 75 && T < 94);
    const int q = lane & 3, lr = lane >> 2;
    const bool owner = isG && ((lane & 15) < 4);
    const uint32_t lm_off = (uint32_t)((lane & 15) * 32 + (lane >> 4) * 16);
    const uint32_t Abase = sb + wid * 19456;

    const int uA = 4 * T + ((lane < 16) ? 0 : 1), uB = uA + 2;
    float bG[8];
    if (owner) {
        #pragma unroll
        for (int g = 0; g < 4; ++g) { bG[g] = biasf_g[uA * 4 + g]; bG[4 + g] = biasf_g[uB * 4 + g]; }
    }
    const int n0r = isO ? (16 * (T - 75) + lr) : 0, n1r = n0r + 8;
    const float bo0 = (isO && n0r < HH) ? b_out[n0r] : 0.f;
    const float bo1 = (isO && n1r < HH) ? b_out[n1r] : 0.f;

    for (int j = 1; j <= steps; ++j) {
        const float* hsrc = (j & 1) ? hP1_g : hP0_g;
        float* hdst = (j & 1) ? hP0_g : hP1_g;

        for (int cg = 0; cg < 8; ++cg) {        // 8 passes x 16 rows
            // ---- stage 16 rows: coalesced, no div/mod ----
            #pragma unroll 4
            for (int r = 0; r < 16; ++r) {
                const float* hrow = hsrc + (size_t)(r0set + cg * 16 + r) * HH;
                char* dH = sm + SM_HSTH + r * 608;
                char* dL = sm + SM_HSTL + r * 608;
                for (int u = tid; u < HH; u += NTW) {
                    float h = __ldg(&hrow[u]);
                    __nv_bfloat16 hh = __float2bfloat16(h);
                    *(__nv_bfloat16*)(dH + u * 2) = hh;
                    *(__nv_bfloat16*)(dL + u * 2) =
                        __float2bfloat16(h - __bfloat162float(hh));
                }
            }
            __syncthreads();

            float dA1[4] = {0,0,0,0}, dA2[4] = {0,0,0,0}, dA3[4] = {0,0,0,0};
            float dB1[4] = {0,0,0,0}, dB2[4] = {0,0,0,0}, dB3[4] = {0,0,0,0};
            if (isG || isO) {
                const char* hstH = sm + SM_HSTH;
                const char* hstL = sm + SM_HSTL;
                const uint32_t rbA = (uint32_t)(lr * 608);
                const uint32_t rbB = (uint32_t)((lr + 8) * 608);
                #pragma unroll 19
                for (int kt = 0; kt < 19; ++kt) {
                    uint32_t ah[4], al[4];
                    ldsm4(ah, Abase + kt * 1024 + lm_off);
                    ldsm4(al, Abase + kt * 1024 + 512 + lm_off);
                    uint32_t u0 = (uint32_t)((kt * 16 + 2 * q) * 2);
                    uint32_t u1 = u0 + 16;
                    uint32_t bh0a = *(const uint32_t*)(hstH + rbA + u0);
                    uint32_t bh1a = *(const uint32_t*)(hstH + rbA + u1);
                    uint32_t bl0a = *(const uint32_t*)(hstL + rbA + u0);
                    uint32_t bl1a = *(const uint32_t*)(hstL + rbA + u1);
                    uint32_t bh0b = *(const uint32_t*)(hstH + rbB + u0);
                    uint32_t bh1b = *(const uint32_t*)(hstH + rbB + u1);
                    uint32_t bl0b = *(const uint32_t*)(hstL + rbB + u0);
                    uint32_t bl1b = *(const uint32_t*)(hstL + rbB + u1);
                    mma16(dA1, ah, bh0a, bh1a);
                    mma16(dB1, ah, bh0b, bh1b);
                    mma16(dA2, ah, bl0a, bl1a);
                    mma16(dB2, ah, bl0b, bl1b);
                    mma16(dA3, al, bh0a, bh1a);
                    mma16(dB3, al, bh0b, bh1b);
                }
            }
            float dA[4], dB[4];
            #pragma unroll
            for (int p = 0; p < 4; ++p) {
                dA[p] = dA1[p] + dA2[p] + dA3[p];
                dB[p] = dB1[p] + dB2[p] + dB3[p];
            }

            if (isO) {
                #pragma unroll
                for (int ch = 0; ch < 2; ++ch) {
                    float* dd = ch ? dB : dA;
                    float* orow = out + ((size_t)(j - 1) * B + r0set + cg * 16 + ch * 8) * HH;
                    if (n0r < HH) {
                        orow[(size_t)(2 * q) * HH + n0r] = dd[0] + bo0;
                        orow[(size_t)(2 * q + 1) * HH + n0r] = dd[1] + bo0;
                    }
                    if (n1r < HH) {
                        orow[(size_t)(2 * q) * HH + n1r] = dd[2] + bo1;
                        orow[(size_t)(2 * q + 1) * HH + n1r] = dd[3] + bo1;
                    }
                }
            }
            if (isG && j < steps) {
                #pragma unroll
                for (int ch = 0; ch < 2; ++ch) {
                    float* dd = ch ? dB : dA;
                    float fv[4], gv[4], ov[4];
                    #pragma unroll
                    for (int p = 0; p < 4; ++p) {
                        fv[p] = __shfl_down_sync(0xffffffffu, dd[p], 4);
                        gv[p] = __shfl_down_sync(0xffffffffu, dd[p], 8);
                        ov[p] = __shfl_down_sync(0xffffffffu, dd[p], 12);
                    }
                    if (owner) {
                        #pragma unroll
                        for (int c4 = 0; c4 < 4; ++c4) {
                            int ui = c4 >> 1, nn = c4 & 1;
                            int u = ui ? uB : uA;
                            int ns = cg * 16 + ch * 8 + 2 * q + nn;
                            float ii = sigf(dd[c4] + bG[ui * 4 + 0]);
                            float ff = sigf(fv[c4] + bG[ui * 4 + 1]);
                            float gg = tanhf_fast(gv[c4] + bG[ui * 4 + 2]);
                            float oo = sigf(ov[c4] + bG[ui * 4 + 3]);
                            float* cs = &c_sm[(u - rank * 24) * 128 + ns];
                            float cc = fmaf(ff, *cs, ii * gg);
                            *cs = cc;
                            hdst[(size_t)(r0set + ns) * HH + u] = oo * tanhf_fast(cc);
                        }
                    }
                }
            }
            __syncthreads();   // staging reuse
        }

        // ---- grid barrier (monotonic counter; 128 CTAs co-resident) ----
        __threadfence();
        __syncthreads();
        if (tid == 0) {
            atomicAdd(&bar_cnt_g, 1u);
            unsigned target = NB * (unsigned)j;
            unsigned v;
            do {
                asm volatile("ld.global.acquire.gpu.u32 %0, [%1];"
                             : "=r"(v) : "l"(&bar_cnt_g));
                if (v < target) __nanosleep(32);
            } while (v < target);
        }
        __syncthreads();
    }
}

// ---------------- launch ----------------
extern "C" void kernel_launch(void* const* d_in, const int* in_sizes, int n_in,
                              void* d_out, int out_size) {
    const float* h0 = (const float*)d_in[0];
    const float* c0 = (const float*)d_in[1];
    const float* start = (const float*)d_in[2];
    const float* W_ih = (const float*)d_in[3];
    const float* W_hh = (const float*)d_in[4];
    const float* b_ih = (const float*)d_in[5];
    const float* b_hh = (const float*)d_in[6];
    const float* W_out = (const float*)d_in[7];
    const float* b_out = (const float*)d_in[8];
    int B = in_sizes[0] / HH;            // 1024
    int steps = out_size / (B * HH);     // 256

    int pe = 600 * G4 + G4;
    prep_basic<<<(pe + 255) / 256, 256>>>(W_ih, W_hh, b_ih, b_hh);
    dim3 fg(G4 / 16, HH / 20);
    prep_fold<<<fg, 320>>>(W_ih, W_hh, W_out);
    prep_biasf<<<(G4 + 255) / 256, 256>>>(W_ih, b_ih, b_hh, b_out);
    prep_pack<<<(96 * 9728 + 255) / 256, 256>>>(W_out);
    reset_bar<<<1, 1>>>();
    step0<<<B / 8, 320>>>(h0, c0, start, B);

    cudaFuncSetAttribute(lstm_hmma, cudaFuncAttributeMaxDynamicSharedMemorySize, SM_TOT);
    int grid = 16 * (B / 128);           // 128 CTAs, all co-resident on 148 SMs
    lstm_hmma<<<grid, NTW, SM_TOT>>>(b_out, (float*)d_out, B, steps);
}

// round 13
// speedup vs baseline: 1.8009x; 1.8009x over previous
#include <cuda_runtime.h>
#include <cuda_bf16.h>
#include <cstdint>

#define HH 300
#define G4 1200
#define NTW 384                 // 12 warps: (tile 0..5) x (row-half 0..1)

// SMEM offsets (bytes)
#define SM_A    0               // 6 tiles x 19456 = 116736
#define SM_HST  116736          // 2 halves x (hi 9728 + lo 9728) = 38912
#define SM_C    155648          // c-state: 24 units x 128 rows x f32 = 12288
#define SM_TOT  167936

__device__ __align__(256) float Wt2_g[600 * G4];   // step0 weights [k][u*4+g]
__device__ __align__(256) float Wc2_g[HH * G4];    // folded [k][u*4+g]
__device__ __align__(256) float bias2_g[G4];
__device__ __align__(256) float biasf_g[G4];
__device__ __align__(256) __nv_bfloat16 AT_g[96 * 9728];  // [tile][kt][hl][r16][k16]
__device__ float c1_g[1024 * HH];
__device__ float hP0_g[1024 * HH];
__device__ float hP1_g[1024 * HH];
__device__ unsigned bar_set_g[8 * 32];             // one padded counter per set

__device__ __forceinline__ uint32_t smem_u32(const void* p) {
    uint32_t a;
    asm("{ .reg .u64 t; cvta.to.shared.u64 t, %1; cvt.u32.u64 %0, t; }" : "=r"(a) : "l"(p));
    return a;
}
__device__ __forceinline__ float sigf(float x) {
    return __fdividef(1.0f, 1.0f + __expf(-x));
}
__device__ __forceinline__ float tanhf_fast(float x) {
    return 1.0f - 2.0f * __fdividef(1.0f, __expf(2.0f * x) + 1.0f);
}
__device__ __forceinline__ void ldsm4(uint32_t* a, uint32_t addr) {
    asm volatile("ldmatrix.sync.aligned.m8n8.x4.shared.b16 {%0,%1,%2,%3},[%4];"
                 : "=r"(a[0]), "=r"(a[1]), "=r"(a[2]), "=r"(a[3]) : "r"(addr));
}
__device__ __forceinline__ void mma16(float* d, const uint32_t* a, uint32_t b0, uint32_t b1) {
    asm volatile(
        "mma.sync.aligned.m16n8k16.row.col.f32.bf16.bf16.f32 "
        "{%0,%1,%2,%3},{%4,%5,%6,%7},{%8,%9},{%0,%1,%2,%3};"
        : "+f"(d[0]), "+f"(d[1]), "+f"(d[2]), "+f"(d[3])
        : "r"(a[0]), "r"(a[1]), "r"(a[2]), "r"(a[3]), "r"(b0), "r"(b1));
}

// ---------------- prep (identical to passing R11) ----------------
__global__ void prep_basic(const float* W_ih, const float* W_hh, const float* b_ih,
                           const float* b_hh) {
    int idx = blockIdx.x * blockDim.x + threadIdx.x;
    if (idx < 600 * G4) {
        int k = idx / G4, col = idx % G4, u = col >> 2, g = col & 3, n = u + HH * g;
        Wt2_g[idx] = (k < HH) ? W_ih[n * HH + k] : W_hh[n * HH + (k - HH)];
    }
    int i3 = idx - 600 * G4;
    if (i3 >= 0 && i3 < G4) {
        int u = i3 >> 2, g = i3 & 3;
        bias2_g[i3] = b_ih[u + HH * g] + b_hh[u + HH * g];
    }
}
__global__ void prep_fold(const float* W_ih, const float* W_hh, const float* W_out) {
    __shared__ float sw[HH][20];
    int tid = threadIdx.x, kk = tid % 20, c = tid / 20;
    int k = blockIdx.y * 20 + kk, col = blockIdx.x * 16 + c;
    int u = col >> 2, g = col & 3, n = u + HH * g;
    for (int i = tid; i < HH * 20; i += 320)
        sw[i / 20][i % 20] = W_out[(i / 20) * HH + blockIdx.y * 20 + (i % 20)];
    __syncthreads();
    float acc = W_hh[n * HH + k];
    const float* wr = &W_ih[n * HH];
    #pragma unroll 4
    for (int j = 0; j < HH; ++j) acc = fmaf(__ldg(&wr[j]), sw[j][kk], acc);
    Wc2_g[k * G4 + col] = acc;
}
__global__ void prep_biasf(const float* W_ih, const float* b_ih, const float* b_hh,
                           const float* b_out) {
    int col = blockIdx.x * blockDim.x + threadIdx.x;
    if (col >= G4) return;
    int u = col >> 2, g = col & 3, n = u + HH * g;
    float acc = b_ih[n] + b_hh[n];
    const float* wr = &W_ih[n * HH];
    #pragma unroll 4
    for (int j = 0; j < HH; ++j) acc = fmaf(__ldg(&wr[j]), __ldg(&b_out[j]), acc);
    biasf_g[col] = acc;
}
__global__ void prep_pack(const float* W_out) {
    int idx = blockIdx.x * blockDim.x + threadIdx.x;
    if (idx >= 96 * 9728) return;
    int t = idx / 9728, e = idx % 9728;
    int kt = e >> 9, e2 = e & 511, half = e2 >> 8, e3 = e2 & 255, r = e3 >> 4, k16 = e3 & 15;
    int k = kt * 16 + k16;
    float v = 0.f;
    if (t < 75) {
        int c = 16 * t + r;
        if (k < HH) v = Wc2_g[k * G4 + c];
    } else if (t < 94) {
        int n = 16 * (t - 75) + r;
        if (n < HH && k < HH) v = W_out[n * HH + k];
    }
    __nv_bfloat16 hi = __float2bfloat16(v);
    AT_g[idx] = half ? __float2bfloat16(v - __bfloat162float(hi)) : hi;
}
__global__ void reset_bar() {
    int i = threadIdx.x;
    if (i < 8 * 32) bar_set_g[i] = 0u;
}

// ---------------- step 0 (K=600, exact fp32) -> h1 (hP1), c1 ----------------
__global__ void __launch_bounds__(320, 1)
step0(const float* h0, const float* c0, const float* start, int B) {
    __shared__ float xh[600 * 8];
    int tid = threadIdx.x, r0 = blockIdx.x * 8;
    for (int idx = tid; idx < HH * 8; idx += 320) {
        int u = idx >> 3, b = idx & 7;
        xh[u * 8 + b] = start[(size_t)(r0 + b) * HH + u];
        xh[(HH + u) * 8 + b] = h0[(size_t)(r0 + b) * HH + u];
    }
    __syncthreads();
    if (tid < HH) {
        float a0[8], a1[8], a2[8], a3[8];
        float4 bb = *(const float4*)&bias2_g[tid * 4];
        #pragma unroll
        for (int b = 0; b < 8; ++b) { a0[b] = bb.x; a1[b] = bb.y; a2[b] = bb.z; a3[b] = bb.w; }
        for (int k = 0; k < 600; ++k) {
            float4 wv = *(const float4*)&Wt2_g[k * G4 + tid * 4];
            #pragma unroll
            for (int b = 0; b < 8; ++b) {
                float xv = xh[k * 8 + b];
                a0[b] = fmaf(xv, wv.x, a0[b]); a1[b] = fmaf(xv, wv.y, a1[b]);
                a2[b] = fmaf(xv, wv.z, a2[b]); a3[b] = fmaf(xv, wv.w, a3[b]);
            }
        }
        #pragma unroll
        for (int b = 0; b < 8; ++b) {
            float iv = sigf(a0[b]), fv = sigf(a1[b]);
            float gv = tanhf_fast(a2[b]), ov = sigf(a3[b]);
            float cc = fmaf(fv, c0[(size_t)(r0 + b) * HH + tid], iv * gv);
            hP1_g[(size_t)(r0 + b) * HH + tid] = ov * tanhf_fast(cc);
            c1_g[(size_t)(r0 + b) * HH + tid] = cc;
        }
    }
}

// ---------------- persistent HMMA kernel ----------------
// 128 CTAs = 8 sets x 16 ranks. rank -> 6 resident tiles; set -> 128 batch rows.
// 12 warps: warp = (tile wt, row-half). 4 passes/iter of 16 rows per half.
__global__ void __launch_bounds__(NTW, 1)
lstm_hmma(const float* __restrict__ b_out, float* __restrict__ out, int B, int steps) {
    extern __shared__ char sm[];
    const uint32_t sb = smem_u32(sm);
    const int tid = threadIdx.x, wid = tid >> 5, lane = tid & 31;
    const int rank = blockIdx.x & 15;
    const int set = blockIdx.x >> 4;
    const int r0set = set * 128;
    float* c_sm = (float*)(sm + SM_C);

    // resident A tiles
    {
        const uint4* src = (const uint4*)(AT_g + (size_t)rank * 6 * 9728);
        uint4* dst = (uint4*)sm;
        for (int i = tid; i < 7296; i += NTW) dst[i] = src[i];
    }
    // zero staging (pad units 300-303 never rewritten -> stay 0)
    for (int i = tid; i < 38912 / 4; i += NTW) ((uint32_t*)(sm + SM_HST))[i] = 0;
    // c-state init
    for (int i = tid; i < 24 * 128; i += NTW) {
        int ul = i >> 7, ns = i & 127, u = rank * 24 + ul;
        if (u < HH) c_sm[i] = c1_g[(size_t)(r0set + ns) * HH + u];
    }
    __syncthreads();

    const int wt = wid % 6;                 // tile slot
    const int half = wid / 6;               // row half (0/1): rows [64*half, 64*half+64)
    const int T = rank * 6 + wt;
    const bool isG = (T < 75), isO = (T >= 75 && T < 94);
    const int q = lane & 3, lr = lane >> 2;
    const bool owner = isG && ((lane & 15) < 4);
    const uint32_t lm_off = (uint32_t)((lane & 15) * 32 + (lane >> 4) * 16);
    const uint32_t Abase = sb + wt * 19456;
    const uint32_t HstH = (uint32_t)(SM_HST + half * 19456);
    const uint32_t HstL = HstH + 9728u;

    const int uA = 4 * T + ((lane < 16) ? 0 : 1), uB = uA + 2;
    float bG[8];
    if (owner) {
        #pragma unroll
        for (int g = 0; g < 4; ++g) { bG[g] = biasf_g[uA * 4 + g]; bG[4 + g] = biasf_g[uB * 4 + g]; }
    }
    const int n0r = isO ? (16 * (T - 75) + lr) : 0, n1r = n0r + 8;
    const float bo0 = (isO && n0r < HH) ? b_out[n0r] : 0.f;
    const float bo1 = (isO && n1r < HH) ? b_out[n1r] : 0.f;

    unsigned* barp = &bar_set_g[set * 32];

    for (int j = 1; j <= steps; ++j) {
        const float* hsrc = (j & 1) ? hP1_g : hP0_g;
        float* hdst = (j & 1) ? hP0_g : hP1_g;

        for (int cg = 0; cg < 4; ++cg) {        // 4 passes x (16 rows per half)
            // ---- stage 32 rows (both halves) cooperatively ----
            for (int i = tid; i < 9600; i += NTW) {
                int rr = i / 300, u = i - rr * 300;          // const-div -> mulhi
                int hf = rr >> 4, rl = rr & 15;
                float h = __ldg(&hsrc[(size_t)(r0set + hf * 64 + cg * 16 + rl) * HH + u]);
                __nv_bfloat16 hh = __float2bfloat16(h);
                uint32_t o = (uint32_t)(SM_HST + hf * 19456 + rl * 608 + u * 2);
                *(__nv_bfloat16*)(sm + o) = hh;
                *(__nv_bfloat16*)(sm + o + 9728) =
                    __float2bfloat16(h - __bfloat162float(hh));
            }
            __syncthreads();

            float dA1[4] = {0,0,0,0}, dA2[4] = {0,0,0,0}, dA3[4] = {0,0,0,0};
            float dB1[4] = {0,0,0,0}, dB2[4] = {0,0,0,0}, dB3[4] = {0,0,0,0};
            if (isG || isO) {
                const uint32_t rbA = HstH + (uint32_t)(lr * 608);
                const uint32_t rbB = HstH + (uint32_t)((lr + 8) * 608);
                const uint32_t rlA = HstL + (uint32_t)(lr * 608);
                const uint32_t rlB = HstL + (uint32_t)((lr + 8) * 608);
                #pragma unroll 4
                for (int kt = 0; kt < 19; ++kt) {
                    uint32_t ah[4], al[4];
                    ldsm4(ah, Abase + kt * 1024 + lm_off);
                    ldsm4(al, Abase + kt * 1024 + 512 + lm_off);
                    uint32_t u0 = (uint32_t)((kt * 16 + 2 * q) * 2);
                    uint32_t u1 = u0 + 16;
                    uint32_t bh0a = *(const uint32_t*)(sm + rbA + u0);
                    uint32_t bh1a = *(const uint32_t*)(sm + rbA + u1);
                    uint32_t bl0a = *(const uint32_t*)(sm + rlA + u0);
                    uint32_t bl1a = *(const uint32_t*)(sm + rlA + u1);
                    uint32_t bh0b = *(const uint32_t*)(sm + rbB + u0);
                    uint32_t bh1b = *(const uint32_t*)(sm + rbB + u1);
                    uint32_t bl0b = *(const uint32_t*)(sm + rlB + u0);
                    uint32_t bl1b = *(const uint32_t*)(sm + rlB + u1);
                    mma16(dA1, ah, bh0a, bh1a);
                    mma16(dB1, ah, bh0b, bh1b);
                    mma16(dA2, ah, bl0a, bl1a);
                    mma16(dB2, ah, bl0b, bl1b);
                    mma16(dA3, al, bh0a, bh1a);
                    mma16(dB3, al, bh0b, bh1b);
                }
            }
            float dA[4], dB[4];
            #pragma unroll
            for (int p = 0; p < 4; ++p) {
                dA[p] = dA1[p] + dA2[p] + dA3[p];
                dB[p] = dB1[p] + dB2[p] + dB3[p];
            }

            const int rowbase = half * 64 + cg * 16;
            if (isO) {
                #pragma unroll
                for (int ch = 0; ch < 2; ++ch) {
                    float* dd = ch ? dB : dA;
                    float* orow = out + ((size_t)(j - 1) * B + r0set + rowbase + ch * 8) * HH;
                    if (n0r < HH) {
                        orow[(size_t)(2 * q) * HH + n0r] = dd[0] + bo0;
                        orow[(size_t)(2 * q + 1) * HH + n0r] = dd[1] + bo0;
                    }
                    if (n1r < HH) {
                        orow[(size_t)(2 * q) * HH + n1r] = dd[2] + bo1;
                        orow[(size_t)(2 * q + 1) * HH + n1r] = dd[3] + bo1;
                    }
                }
            }
            if (isG && j < steps) {
                #pragma unroll
                for (int ch = 0; ch < 2; ++ch) {
                    float* dd = ch ? dB : dA;
                    float fv[4], gv[4], ov[4];
                    #pragma unroll
                    for (int p = 0; p < 4; ++p) {
                        fv[p] = __shfl_down_sync(0xffffffffu, dd[p], 4);
                        gv[p] = __shfl_down_sync(0xffffffffu, dd[p], 8);
                        ov[p] = __shfl_down_sync(0xffffffffu, dd[p], 12);
                    }
                    if (owner) {
                        #pragma unroll
                        for (int c4 = 0; c4 < 4; ++c4) {
                            int ui = c4 >> 1, nn = c4 & 1;
                            int u = ui ? uB : uA;
                            int ns = rowbase + ch * 8 + 2 * q + nn;
                            float ii = sigf(dd[c4] + bG[ui * 4 + 0]);
                            float ff = sigf(fv[c4] + bG[ui * 4 + 1]);
                            float gg = tanhf_fast(gv[c4] + bG[ui * 4 + 2]);
                            float oo = sigf(ov[c4] + bG[ui * 4 + 3]);
                            float* cs = &c_sm[(u - rank * 24) * 128 + ns];
                            float cc = fmaf(ff, *cs, ii * gg);
                            *cs = cc;
                            hdst[(size_t)(r0set + ns) * HH + u] = oo * tanhf_fast(cc);
                        }
                    }
                }
            }
            __syncthreads();   // staging reuse
        }

        // ---- per-set barrier: only the 16 CTAs sharing this batch set ----
        __threadfence();
        __syncthreads();
        if (tid == 0) {
            atomicAdd(barp, 1u);
            unsigned target = 16u * (unsigned)j;
            unsigned v;
            do {
                asm volatile("ld.global.acquire.gpu.u32 %0, [%1];"
                             : "=r"(v) : "l"(barp));
            } while (v < target);
        }
        __syncthreads();
    }
}

// ---------------- launch ----------------
extern "C" void kernel_launch(void* const* d_in, const int* in_sizes, int n_in,
                              void* d_out, int out_size) {
    const float* h0 = (const float*)d_in[0];
    const float* c0 = (const float*)d_in[1];
    const float* start = (const float*)d_in[2];
    const float* W_ih = (const float*)d_in[3];
    const float* W_hh = (const float*)d_in[4];
    const float* b_ih = (const float*)d_in[5];
    const float* b_hh = (const float*)d_in[6];
    const float* W_out = (const float*)d_in[7];
    const float* b_out = (const float*)d_in[8];
    int B = in_sizes[0] / HH;            // 1024
    int steps = out_size / (B * HH);     // 256

    int pe = 600 * G4 + G4;
    prep_basic<<<(pe + 255) / 256, 256>>>(W_ih, W_hh, b_ih, b_hh);
    dim3 fg(G4 / 16, HH / 20);
    prep_fold<<<fg, 320>>>(W_ih, W_hh, W_out);
    prep_biasf<<<(G4 + 255) / 256, 256>>>(W_ih, b_ih, b_hh, b_out);
    prep_pack<<<(96 * 9728 + 255) / 256, 256>>>(W_out);
    reset_bar<<<1, 256>>>();
    step0<<<B / 8, 320>>>(h0, c0, start, B);

    cudaFuncSetAttribute(lstm_hmma, cudaFuncAttributeMaxDynamicSharedMemorySize, SM_TOT);
    int grid = 16 * (B / 128);           // 128 CTAs, all co-resident on 148 SMs
    lstm_hmma<<<grid, NTW, SM_TOT>>>(b_out, (float*)d_out, B, steps);
}

// round 14
// speedup vs baseline: 2.9392x; 1.6320x over previous
#include <cuda_runtime.h>
#include <cuda_fp16.h>
#include <cstdint>

// Problem constants
#define HH   300
#define G4   1200          // 4*H
#define KK   600           // 2*H (x | h), step-0 only
#define BCH  8             // batch rows per CTA
#define NT   640           // 608 compute + producer warp
#define CHUNK_BYTES 48000
#define NCHUNK 4
#define GT0 60             // step-0 fp32 gates tiles (10 k-rows x 1200 f32)
#define GTF 15             // folded fp16 gates tiles (20 k-rows x 1200 f16)
#define OTF 4              // out fp16 tiles (80,80,80,60 k-rows x 300 f16)
#define TPSF (OTF + GTF)   // 19 per steady step

// SMEM layout (bytes)
#define SM_XH    0                       // 600*8 floats = 19200 B
#define SM_BAR   19200
#define SM_CHUNK 19264
#define SM_TOTAL (SM_CHUNK + NCHUNK*CHUNK_BYTES)   // 211264 B

// Persistent weights (allocation-free rule: __device__ globals)
__device__ __align__(256) float Wt2_g[KK * G4];     // step-0 fp32 [k][u*4+g]
__device__ __align__(256) float Wc2_g[HH * G4];     // folded fp32 (prep only)
__device__ __align__(256) float WoutT_g[HH * HH];   // [k][n] fp32 (prep only)
__device__ __align__(256) __half WcH_g[HH * G4];    // folded fp16 [k][u*4+g]
__device__ __align__(256) __half WoutH_g[HH * HH];  // out fp16 [k][n]
__device__ __align__(256) float bias2_g[G4];
__device__ __align__(256) float biasf_g[G4];

// ---------------- packed f32x2 helpers ----------------
__device__ __forceinline__ unsigned long long pack2(float x, float y) {
    unsigned long long r;
    asm("mov.b64 %0, {%1, %2};" : "=l"(r) : "f"(x), "f"(y));
    return r;
}
__device__ __forceinline__ void ffma2(unsigned long long& d,
                                      unsigned long long a,
                                      unsigned long long b) {
    asm("fma.rn.f32x2 %0, %1, %2, %0;" : "+l"(d) : "l"(a), "l"(b));
}
__device__ __forceinline__ void fadd2(unsigned long long& d, unsigned long long a) {
    asm("add.rn.f32x2 %0, %0, %1;" : "+l"(d) : "l"(a));
}
__device__ __forceinline__ float2 unpack2(unsigned long long v) {
    float2 r;
    asm("mov.b64 {%0, %1}, %2;" : "=f"(r.x), "=f"(r.y) : "l"(v));
    return r;
}
__device__ __forceinline__ float sigf(float x) {
    return __fdividef(1.0f, 1.0f + __expf(-x));
}
__device__ __forceinline__ float tanhf_fast(float x) {
    return 1.0f - 2.0f * __fdividef(1.0f, __expf(2.0f * x) + 1.0f);
}

// ---------------- mbarrier / bulk-copy PTX (proven R5) ----------------
__device__ __forceinline__ uint32_t smem_u32(const void* p) {
    uint32_t a;
    asm("{ .reg .u64 t; cvta.to.shared.u64 t, %1; cvt.u32.u64 %0, t; }"
        : "=r"(a) : "l"(p));
    return a;
}
__device__ __forceinline__ uint32_t ctarank() {
    uint32_t r; asm("mov.u32 %0, %%cluster_ctarank;" : "=r"(r)); return r;
}
__device__ __forceinline__ void mbar_init(uint32_t a, uint32_t cnt) {
    asm volatile("mbarrier.init.shared.b64 [%0], %1;" :: "r"(a), "r"(cnt) : "memory");
}
__device__ __forceinline__ void mbar_expect_tx(uint32_t a, uint32_t bytes) {
    asm volatile("mbarrier.arrive.expect_tx.shared.b64 _, [%0], %1;"
                 :: "r"(a), "r"(bytes) : "memory");
}
__device__ __forceinline__ void mbar_arrive(uint32_t a) {
    asm volatile("mbarrier.arrive.shared.b64 _, [%0];" :: "r"(a) : "memory");
}
__device__ __forceinline__ void mbar_arrive_cluster(uint32_t a, uint32_t rankTgt) {
    asm volatile(
        "{\n\t.reg .b32 r;\n\t"
        "mapa.shared::cluster.u32 r, %0, %1;\n\t"
        "mbarrier.arrive.shared::cluster.b64 _, [r];\n\t}"
        :: "r"(a), "r"(rankTgt) : "memory");
}
__device__ __forceinline__ void mbar_wait_acq(uint32_t a, uint32_t parity) {
    asm volatile(
        "{\n\t.reg .pred P;\n"
        "LW_%=:\n\t"
        "mbarrier.try_wait.parity.acquire.cta.shared::cta.b64 P, [%0], %1, 0x989680;\n\t"
        "@P bra.uni LD_%=;\n\t"
        "bra.uni LW_%=;\n"
        "LD_%=:\n\t}"
        :: "r"(a), "r"(parity) : "memory");
}
__device__ __forceinline__ void mbar_wait_rlx(uint32_t a, uint32_t parity) {
    asm volatile(
        "{\n\t.reg .pred P;\n"
        "LW_%=:\n\t"
        "mbarrier.try_wait.parity.relaxed.cta.shared::cta.b64 P, [%0], %1, 0x989680;\n\t"
        "@P bra.uni LD_%=;\n\t"
        "bra.uni LW_%=;\n"
        "LD_%=:\n\t}"
        :: "r"(a), "r"(parity) : "memory");
}
__device__ __forceinline__ void bulk_mc(uint32_t dst, const void* src,
                                        uint32_t bytes, uint32_t mbar,
                                        uint16_t mask) {
    asm volatile(
        "cp.async.bulk.shared::cluster.global.mbarrier::complete_tx::bytes"
        ".multicast::cluster [%0], [%1], %2, [%3], %4;"
        :: "r"(dst), "l"(src), "r"(bytes), "r"(mbar), "h"(mask) : "memory");
}

// ---------------- prep ----------------
__global__ void prep_basic(const float* __restrict__ W_ih,
                           const float* __restrict__ W_hh,
                           const float* __restrict__ b_ih,
                           const float* __restrict__ b_hh,
                           const float* __restrict__ W_out) {
    int idx = blockIdx.x * blockDim.x + threadIdx.x;
    if (idx < KK * G4) {
        int k = idx / G4, col = idx % G4, u = col >> 2, g = col & 3, n = u + HH * g;
        Wt2_g[idx] = (k < HH) ? W_ih[n * HH + k] : W_hh[n * HH + (k - HH)];
    }
    int i2 = idx - KK * G4;
    if (i2 >= 0 && i2 < HH * HH) {
        int k = i2 / HH, n = i2 % HH;
        WoutT_g[i2] = W_out[n * HH + k];
    }
    int i3 = idx - (KK * G4 + HH * HH);
    if (i3 >= 0 && i3 < G4) {
        int u = i3 >> 2, g = i3 & 3;
        bias2_g[i3] = b_ih[u + HH * g] + b_hh[u + HH * g];
    }
}
__global__ void prep_fold(const float* __restrict__ W_ih,
                          const float* __restrict__ W_hh,
                          const float* __restrict__ W_out) {
    __shared__ float sw[HH][20];
    int tid = threadIdx.x, kk = tid % 20, c = tid / 20;
    int k = blockIdx.y * 20 + kk, col = blockIdx.x * 16 + c;
    int u = col >> 2, g = col & 3, n = u + HH * g;
    for (int i = tid; i < HH * 20; i += 320)
        sw[i / 20][i % 20] = W_out[(i / 20) * HH + blockIdx.y * 20 + (i % 20)];
    __syncthreads();
    float acc = W_hh[n * HH + k];
    const float* wr = &W_ih[n * HH];
    #pragma unroll 4
    for (int j = 0; j < HH; ++j) acc = fmaf(__ldg(&wr[j]), sw[j][kk], acc);
    Wc2_g[k * G4 + col] = acc;
}
__global__ void prep_biasf(const float* __restrict__ W_ih,
                           const float* __restrict__ b_ih,
                           const float* __restrict__ b_hh,
                           const float* __restrict__ b_out) {
    int col = blockIdx.x * blockDim.x + threadIdx.x;
    if (col >= G4) return;
    int u = col >> 2, g = col & 3, n = u + HH * g;
    float acc = b_ih[n] + b_hh[n];
    const float* wr = &W_ih[n * HH];
    #pragma unroll 4
    for (int j = 0; j < HH; ++j) acc = fmaf(__ldg(&wr[j]), __ldg(&b_out[j]), acc);
    biasf_g[col] = acc;
}
__global__ void prep_cvt() {
    int idx = blockIdx.x * blockDim.x + threadIdx.x;
    if (idx < HH * G4) WcH_g[idx] = __float2half(Wc2_g[idx]);
    int i2 = idx - HH * G4;
    if (i2 >= 0 && i2 < HH * HH) WoutH_g[i2] = __float2half(WoutT_g[i2]);
}

// ---------------- main persistent LSTM kernel ----------------
// Pair-column layout (proven R4/R5): even thread of pair holds {i,f} of unit
// u=mc/2, odd holds {g,o}; exchange via shfl.xor 1. Producer = thread 608.
// Step 0: K=600 fp32. Steps t>=1: [4 out-fp16 tiles (out[t-1]=Wout*h_t) +
// 15 gates-fp16 tiles] all reading h_t, then elementwise -> h_{t+1}.
// Tail: 4 out tiles on h_steps -> out[steps-1].
__global__ void __launch_bounds__(NT, 1) __cluster_dims__(2, 1, 1)
lstm_main(const float* __restrict__ h0,
          const float* __restrict__ c0,
          const float* __restrict__ start,
          const float* __restrict__ b_out,
          float* __restrict__ out,
          int B, int steps) {
    extern __shared__ char smem[];
    float* xh = (float*)(smem + SM_XH);
    unsigned long long* xh2 = (unsigned long long*)xh;
    const ulonglong2* xh4 = (const ulonglong2*)xh;

    const uint32_t sbase = smem_u32(smem);
    const uint32_t bar0 = sbase + SM_BAR;
    const int tid = threadIdx.x;
    const int lane = tid & 31;
    const uint32_t rank = ctarank();
    const uint32_t peer = rank ^ 1u;
    const int r0 = blockIdx.x * BCH;
    const int STEADY = (steps - 1) * TPSF;
    const int TOTAL = GT0 + STEADY + OTF;

    const bool comp = (tid < 608);
    const bool act  = (tid < 600);
    const int mc = act ? tid : (tid - 8);
    const int u  = mc >> 1;
    const int par = mc & 1;
    const bool evenT = (par == 0);

    if (tid == 0) {
        #pragma unroll
        for (int s = 0; s < NCHUNK; ++s) {
            mbar_init(bar0 + s * 16, 1);
            mbar_init(bar0 + s * 16 + 8, 38);
        }
    }
    __syncthreads();
    asm volatile("barrier.cluster.arrive.aligned;" ::: "memory");
    asm volatile("barrier.cluster.wait.aligned;" ::: "memory");

    // initial state: x = start (rows 0..299), h = h0 (rows 300..599)
    for (int idx = tid; idx < HH * BCH; idx += NT) {
        int k = idx >> 3, b = idx & 7;
        xh[k * BCH + b]        = start[(size_t)(r0 + b) * HH + k];
        xh[(HH + k) * BCH + b] = h0[(size_t)(r0 + b) * HH + k];
    }
    float cst[BCH];
    unsigned long long pb0[2], pbf[2], pbo = pack2(0.0f, 0.0f);
    if (comp) {
        float2 b0 = *(const float2*)&bias2_g[mc * 2];
        float2 bf = *(const float2*)&biasf_g[mc * 2];
        pb0[0] = pack2(b0.x, b0.x); pb0[1] = pack2(b0.y, b0.y);
        pbf[0] = pack2(bf.x, bf.x); pbf[1] = pack2(bf.y, bf.y);
        if (evenT) {
            float bo = __ldg(&b_out[u]);
            pbo = pack2(bo, bo);        // bias only on even thread (pair reduce)
            #pragma unroll
            for (int b = 0; b < BCH; ++b) cst[b] = c0[(size_t)(r0 + b) * HH + u];
        }
    }
    __syncthreads();

    // producer cursor (thread 608 only)
    int p_slot = 0, p_phase = 1;
    auto produce = [&](int g) {
        mbar_wait_rlx(bar0 + p_slot * 16 + 8, (uint32_t)p_phase);
        const char* src; int bytes = CHUNK_BYTES;
        if (g < GT0) {
            src = (const char*)Wt2_g + (size_t)g * CHUNK_BYTES;
        } else {
            int gf = g - GT0;
            int r = (gf < STEADY) ? (gf % TPSF) : (gf - STEADY);  // tail r in 0..3
            if (gf < STEADY && r >= OTF) {
                src = (const char*)WcH_g + (size_t)(r - OTF) * CHUNK_BYTES;
            } else {
                src = (const char*)WoutH_g + (size_t)r * CHUNK_BYTES;
                if (r == OTF - 1) bytes = 36000;   // 60 k-rows x 300 x 2B
            }
        }
        int half = bytes >> 1;
        uint32_t full = bar0 + p_slot * 16;
        uint32_t dst = sbase + SM_CHUNK + p_slot * CHUNK_BYTES + rank * half;
        mbar_expect_tx(full, (uint32_t)bytes);
        bulk_mc(dst, src + (size_t)rank * half, (uint32_t)half, full, 0x3);
        if (++p_slot == NCHUNK) { p_slot = 0; p_phase ^= 1; }
    };

    if (tid == 608) {
        #pragma unroll
        for (int i = 0; i < NCHUNK; ++i) produce(i);
    }

    int c_slot = 0, c_phase = 0, gi = 0;

    // consume 4 out tiles (fp16), accumulating into oacc
    auto run_out = [&](unsigned long long* oacc) {
        for (int tile = 0; tile < OTF; ++tile) {
            int halfr = (tile < 3) ? 40 : 30;
            if (comp) {
                mbar_wait_acq(bar0 + c_slot * 16, (uint32_t)c_phase);
                const char* cb = smem + SM_CHUNK + c_slot * CHUNK_BYTES;
                #pragma unroll 10
                for (int r = 0; r < halfr; ++r) {
                    int kl = 2 * r + par;
                    int k = tile * 80 + kl;
                    ulonglong2 ha = xh4[(HH + k) * 2];
                    ulonglong2 hb = xh4[(HH + k) * 2 + 1];
                    float w = __half2float(*(const __half*)(cb + kl * 600 + u * 2));
                    unsigned long long wp = pack2(w, w);
                    ffma2(oacc[0], ha.x, wp); ffma2(oacc[1], ha.y, wp);
                    ffma2(oacc[2], hb.x, wp); ffma2(oacc[3], hb.y, wp);
                }
                if (lane == 0) {
                    mbar_arrive(bar0 + c_slot * 16 + 8);
                    mbar_arrive_cluster(bar0 + c_slot * 16 + 8, peer);
                }
            }
            if (tid == 608 && gi + NCHUNK < TOTAL) produce(gi + NCHUNK);
            if (++c_slot == NCHUNK) { c_slot = 0; c_phase ^= 1; }
            ++gi;
        }
    };
    auto write_out = [&](unsigned long long* oacc, int tdst) {
        if (comp) {
            #pragma unroll
            for (int p = 0; p < 4; ++p) {
                unsigned long long o = __shfl_xor_sync(0xffffffffu, oacc[p], 1);
                fadd2(oacc[p], o);
            }
            if (evenT && act) {
                float* orow = out + ((size_t)tdst * B + r0) * HH;
                #pragma unroll
                for (int p = 0; p < 4; ++p) {
                    float2 v = unpack2(oacc[p]);
                    orow[(size_t)(2 * p) * HH + u]     = v.x;
                    orow[(size_t)(2 * p + 1) * HH + u] = v.y;
                }
            }
        }
    };

    for (int t = 0; t < steps; ++t) {
        unsigned long long acc[2][4];

        if (t == 0) {
            // ---- step 0: 60 fp32 tiles, K=600 (x | h) ----
            #pragma unroll
            for (int g = 0; g < 2; ++g)
                #pragma unroll
                for (int p = 0; p < 4; ++p) acc[g][p] = pb0[g];
            for (int tile = 0; tile < GT0; ++tile) {
                if (comp) {
                    mbar_wait_acq(bar0 + c_slot * 16, (uint32_t)c_phase);
                    const char* cb = smem + SM_CHUNK + c_slot * CHUNK_BYTES;
                    #pragma unroll
                    for (int kl = 0; kl < 10; ++kl) {
                        int xi = tile * 10 + kl;
                        ulonglong2 xa = xh4[xi * 2];
                        ulonglong2 xb = xh4[xi * 2 + 1];
                        float2 w = *(const float2*)(cb + kl * 4800 + mc * 8);
                        unsigned long long w0 = pack2(w.x, w.x);
                        unsigned long long w1 = pack2(w.y, w.y);
                        ffma2(acc[0][0], xa.x, w0); ffma2(acc[0][1], xa.y, w0);
                        ffma2(acc[0][2], xb.x, w0); ffma2(acc[0][3], xb.y, w0);
                        ffma2(acc[1][0], xa.x, w1); ffma2(acc[1][1], xa.y, w1);
                        ffma2(acc[1][2], xb.x, w1); ffma2(acc[1][3], xb.y, w1);
                    }
                    if (lane == 0) {
                        mbar_arrive(bar0 + c_slot * 16 + 8);
                        mbar_arrive_cluster(bar0 + c_slot * 16 + 8, peer);
                    }
                }
                if (tid == 608 && gi + NCHUNK < TOTAL) produce(gi + NCHUNK);
                if (++c_slot == NCHUNK) { c_slot = 0; c_phase ^= 1; }
                ++gi;
            }
        } else {
            // ---- steady step: out tiles first (oacc dead before gates acc) ----
            {
                unsigned long long oacc[4];
                #pragma unroll
                for (int p = 0; p < 4; ++p) oacc[p] = pbo;
                run_out(oacc);
                write_out(oacc, t - 1);
            }
            // ---- gates: 15 fp16 tiles, K=300 (h section) ----
            #pragma unroll
            for (int g = 0; g < 2; ++g)
                #pragma unroll
                for (int p = 0; p < 4; ++p) acc[g][p] = pbf[g];
            for (int tile = 0; tile < GTF; ++tile) {
                if (comp) {
                    mbar_wait_acq(bar0 + c_slot * 16, (uint32_t)c_phase);
                    const char* cb = smem + SM_CHUNK + c_slot * CHUNK_BYTES;
                    #pragma unroll 10
                    for (int kl = 0; kl < 20; ++kl) {
                        int xi = HH + tile * 20 + kl;
                        ulonglong2 xa = xh4[xi * 2];
                        ulonglong2 xb = xh4[xi * 2 + 1];
                        __half2 wh = *(const __half2*)(cb + kl * 2400 + mc * 4);
                        float2 wf = __half22float2(wh);
                        unsigned long long w0 = pack2(wf.x, wf.x);
                        unsigned long long w1 = pack2(wf.y, wf.y);
                        ffma2(acc[0][0], xa.x, w0); ffma2(acc[0][1], xa.y, w0);
                        ffma2(acc[0][2], xb.x, w0); ffma2(acc[0][3], xb.y, w0);
                        ffma2(acc[1][0], xa.x, w1); ffma2(acc[1][1], xa.y, w1);
                        ffma2(acc[1][2], xb.x, w1); ffma2(acc[1][3], xb.y, w1);
                    }
                    if (lane == 0) {
                        mbar_arrive(bar0 + c_slot * 16 + 8);
                        mbar_arrive_cluster(bar0 + c_slot * 16 + 8, peer);
                    }
                }
                if (tid == 608 && gi + NCHUNK < TOTAL) produce(gi + NCHUNK);
                if (++c_slot == NCHUNK) { c_slot = 0; c_phase ^= 1; }
                ++gi;
            }
        }
        __syncthreads();   // all reads of h_t done before overwrite

        // ---- elementwise LSTM (pair shuffle exchange) -> h_{t+1} ----
        if (comp) {
            unsigned long long rg[2][4];
            #pragma unroll
            for (int g = 0; g < 2; ++g)
                #pragma unroll
                for (int p = 0; p < 4; ++p)
                    rg[g][p] = __shfl_xor_sync(0xffffffffu, acc[g][p], 1);
            if (evenT) {
                #pragma unroll
                for (int p = 0; p < 4; ++p) {
                    float2 iv = unpack2(acc[0][p]);
                    float2 fv = unpack2(acc[1][p]);
                    float2 gv = unpack2(rg[0][p]);
                    float2 ov = unpack2(rg[1][p]);
                    float cx = sigf(fv.x) * cst[2*p]   + sigf(iv.x) * tanhf_fast(gv.x);
                    float cy = sigf(fv.y) * cst[2*p+1] + sigf(iv.y) * tanhf_fast(gv.y);
                    cst[2*p] = cx; cst[2*p+1] = cy;
                    float hx = sigf(ov.x) * tanhf_fast(cx);
                    float hy = sigf(ov.y) * tanhf_fast(cy);
                    if (act) xh2[(HH + u) * 4 + p] = pack2(hx, hy);
                }
            }
        }
        __syncthreads();   // h_{t+1} visible
    }

    // ---- tail: out[steps-1] = W_out * h_steps ----
    {
        unsigned long long oacc[4];
        #pragma unroll
        for (int p = 0; p < 4; ++p) oacc[p] = pbo;
        run_out(oacc);
        write_out(oacc, steps - 1);
    }

    asm volatile("barrier.cluster.arrive.aligned;" ::: "memory");
    asm volatile("barrier.cluster.wait.aligned;" ::: "memory");
}

// ---------------- launch ----------------
extern "C" void kernel_launch(void* const* d_in, const int* in_sizes, int n_in,
                              void* d_out, int out_size) {
    const float* h0    = (const float*)d_in[0];
    const float* c0    = (const float*)d_in[1];
    const float* start = (const float*)d_in[2];
    const float* W_ih  = (const float*)d_in[3];
    const float* W_hh  = (const float*)d_in[4];
    const float* b_ih  = (const float*)d_in[5];
    const float* b_hh  = (const float*)d_in[6];
    const float* W_out = (const float*)d_in[7];
    const float* b_out = (const float*)d_in[8];

    int B = in_sizes[0] / HH;            // 1024
    int steps = out_size / (B * HH);     // 256

    int prep_elems = KK * G4 + HH * HH + G4;
    prep_basic<<<(prep_elems + 255) / 256, 256>>>(W_ih, W_hh, b_ih, b_hh, W_out);
    dim3 fg(G4 / 16, HH / 20);
    prep_fold<<<fg, 320>>>(W_ih, W_hh, W_out);
    prep_biasf<<<(G4 + 255) / 256, 256>>>(W_ih, b_ih, b_hh, b_out);
    int cvt_elems = HH * G4 + HH * HH;
    prep_cvt<<<(cvt_elems + 255) / 256, 256>>>();

    cudaFuncSetAttribute(lstm_main, cudaFuncAttributeMaxDynamicSharedMemorySize,
                         SM_TOTAL);
    lstm_main<<<B / BCH, NT, SM_TOTAL>>>(h0, c0, start, b_out,
                                         (float*)d_out, B, steps);
}

// round 15
// speedup vs baseline: 6.1592x; 2.0956x over previous
#include <cuda_runtime.h>
#include <cuda_fp16.h>
#include <cstdint>

#define HH 300
#define G4 1200
#define NT 640              // 19 compute warps + producer warp 19
#define NCHUNK 4
#define CHUNK_MAX 48128     // steady chunk: 94 atoms x 512B

// SMEM layout (bytes)
#define SM_HX    0          // B matrix: 8 rows x 1216B (608 fp16: x 0-303, h 304-607)
#define SM_BAR   9728       // 4 x (full u64, empty u64)
#define SM_BIAS  9792       // biasf 4800 + bias2 4800
#define SM_CHUNK 19392
#define SM_TOTAL (SM_CHUNK + NCHUNK*CHUNK_MAX)   // 211904

// persistent globals (allocation-free rule)
__device__ __align__(256) float Wt2_g[600 * G4];   // [k][u*4+g] k<300:x, >=300:h
__device__ __align__(256) float Wc2_g[HH * G4];    // folded
__device__ __align__(256) float WoutT_g[HH * HH];  // [k][n]
__device__ __align__(256) float bias2_g[G4];
__device__ __align__(256) float biasf_g[G4];
__device__ __align__(256) __half A0_g[2850 * 256];   // step0: [j 0..37][t 0..74] atoms
__device__ __align__(256) __half ASTD_g[1786 * 256]; // steady: [j 0..18][t 0..93] atoms

__device__ __forceinline__ uint32_t smem_u32(const void* p) {
    uint32_t a;
    asm("{ .reg .u64 t; cvta.to.shared.u64 t, %1; cvt.u32.u64 %0, t; }" : "=r"(a) : "l"(p));
    return a;
}
__device__ __forceinline__ uint32_t ctarank() {
    uint32_t r; asm("mov.u32 %0, %%cluster_ctarank;" : "=r"(r)); return r;
}
__device__ __forceinline__ float sigf(float x) {
    return __fdividef(1.0f, 1.0f + __expf(-x));
}
__device__ __forceinline__ float tanhf_fast(float x) {
    return 1.0f - 2.0f * __fdividef(1.0f, __expf(2.0f * x) + 1.0f);
}
__device__ __forceinline__ void ldsm4(uint32_t* a, uint32_t addr) {
    asm volatile("ldmatrix.sync.aligned.m8n8.x4.shared.b16 {%0,%1,%2,%3},[%4];"
                 : "=r"(a[0]), "=r"(a[1]), "=r"(a[2]), "=r"(a[3]) : "r"(addr));
}
__device__ __forceinline__ void mma16(float* d, const uint32_t* a, uint32_t b0, uint32_t b1) {
    asm volatile(
        "mma.sync.aligned.m16n8k16.row.col.f32.f16.f16.f32 "
        "{%0,%1,%2,%3},{%4,%5,%6,%7},{%8,%9},{%0,%1,%2,%3};"
        : "+f"(d[0]), "+f"(d[1]), "+f"(d[2]), "+f"(d[3])
        : "r"(a[0]), "r"(a[1]), "r"(a[2]), "r"(a[3]), "r"(b0), "r"(b1));
}
__device__ __forceinline__ void mbar_init(uint32_t a, uint32_t c) {
    asm volatile("mbarrier.init.shared.b64 [%0], %1;" :: "r"(a), "r"(c) : "memory");
}
__device__ __forceinline__ void mbar_expect_tx(uint32_t a, uint32_t b) {
    asm volatile("mbarrier.arrive.expect_tx.shared.b64 _, [%0], %1;" :: "r"(a), "r"(b) : "memory");
}
__device__ __forceinline__ void mbar_arrive(uint32_t a) {
    asm volatile("mbarrier.arrive.shared.b64 _, [%0];" :: "r"(a) : "memory");
}
__device__ __forceinline__ void mbar_arrive_cluster(uint32_t a, uint32_t rk) {
    asm volatile(
        "{\n\t.reg .b32 r;\n\t"
        "mapa.shared::cluster.u32 r, %0, %1;\n\t"
        "mbarrier.arrive.shared::cluster.b64 _, [r];\n\t}" :: "r"(a), "r"(rk) : "memory");
}
__device__ __forceinline__ void mbar_wait_acq(uint32_t a, uint32_t par) {
    asm volatile(
        "{ .reg .pred P;\nLW_%=:\n"
        "mbarrier.try_wait.parity.acquire.cta.shared::cta.b64 P, [%0], %1, 0x989680;\n"
        "@P bra.uni LD_%=;\nbra.uni LW_%=;\nLD_%=:\n}" :: "r"(a), "r"(par) : "memory");
}
__device__ __forceinline__ void mbar_wait_rlx(uint32_t a, uint32_t par) {
    asm volatile(
        "{ .reg .pred P;\nLW_%=:\n"
        "mbarrier.try_wait.parity.relaxed.cta.shared::cta.b64 P, [%0], %1, 0x989680;\n"
        "@P bra.uni LD_%=;\nbra.uni LW_%=;\nLD_%=:\n}" :: "r"(a), "r"(par) : "memory");
}
__device__ __forceinline__ void bulk_mc(uint32_t dst, const void* src, uint32_t bytes,
                                        uint32_t mbar, uint16_t m) {
    asm volatile(
        "cp.async.bulk.shared::cluster.global.mbarrier::complete_tx::bytes"
        ".multicast::cluster [%0], [%1], %2, [%3], %4;"
        :: "r"(dst), "l"(src), "r"(bytes), "r"(mbar), "h"(m) : "memory");
}

// ---------------- prep (fold/basic proven since R5) ----------------
__global__ void prep_basic(const float* W_ih, const float* W_hh, const float* b_ih,
                           const float* b_hh, const float* W_out) {
    int idx = blockIdx.x * blockDim.x + threadIdx.x;
    if (idx < 600 * G4) {
        int k = idx / G4, col = idx % G4, u = col >> 2, g = col & 3, n = u + HH * g;
        Wt2_g[idx] = (k < HH) ? W_ih[n * HH + k] : W_hh[n * HH + (k - HH)];
    }
    int i2 = idx - 600 * G4;
    if (i2 >= 0 && i2 < HH * HH) WoutT_g[i2] = W_out[(i2 % HH) * HH + (i2 / HH)];
    int i3 = idx - (600 * G4 + HH * HH);
    if (i3 >= 0 && i3 < G4) {
        int u = i3 >> 2, g = i3 & 3;
        bias2_g[i3] = b_ih[u + HH * g] + b_hh[u + HH * g];
    }
}
__global__ void prep_fold(const float* W_ih, const float* W_hh, const float* W_out) {
    __shared__ float sw[HH][20];
    int tid = threadIdx.x, kk = tid % 20, c = tid / 20;
    int k = blockIdx.y * 20 + kk, col = blockIdx.x * 16 + c;
    int u = col >> 2, g = col & 3, n = u + HH * g;
    for (int i = tid; i < HH * 20; i += 320)
        sw[i / 20][i % 20] = W_out[(i / 20) * HH + blockIdx.y * 20 + (i % 20)];
    __syncthreads();
    float acc = W_hh[n * HH + k];
    const float* wr = &W_ih[n * HH];
    #pragma unroll 4
    for (int j = 0; j < HH; ++j) acc = fmaf(__ldg(&wr[j]), sw[j][kk], acc);
    Wc2_g[k * G4 + col] = acc;
}
__global__ void prep_biasf(const float* W_ih, const float* b_ih, const float* b_hh,
                           const float* b_out) {
    int col = blockIdx.x * blockDim.x + threadIdx.x;
    if (col >= G4) return;
    int u = col >> 2, g = col & 3, n = u + HH * g;
    float acc = b_ih[n] + b_hh[n];
    const float* wr = &W_ih[n * HH];
    #pragma unroll 4
    for (int j = 0; j < HH; ++j) acc = fmaf(__ldg(&wr[j]), __ldg(&b_out[j]), acc);
    biasf_g[col] = acc;
}
// pack fp16 HMMA atoms (16x16 half, row stride 32B)
__global__ void prep_pack() {
    int idx = blockIdx.x * blockDim.x + threadIdx.x;
    if (idx >= (2850 + 1786) * 256) return;
    int atom = idx >> 8, e = idx & 255, r = e >> 4, k16 = e & 15;
    float w = 0.f;
    if (atom < 2850) {                 // step0: j 0..37, t 0..74
        int j = atom / 75, t = atom - j * 75, col = 16 * t + r;
        if (j < 19) { int k = j * 16 + k16; if (k < 300) w = Wt2_g[k * G4 + col]; }
        else { int k = 300 + (j - 19) * 16 + k16; if (k < 600) w = Wt2_g[k * G4 + col]; }
        A0_g[idx] = __float2half(w);
    } else {                           // steady: j 0..18, t 0..93
        int a2 = atom - 2850;
        int j = a2 / 94, t = a2 - j * 94, k = j * 16 + k16;
        if (t < 75) { int col = 16 * t + r; if (k < 300) w = Wc2_g[k * G4 + col]; }
        else { int n = 16 * (t - 75) + r; if (k < 300 && n < 300) w = WoutT_g[k * HH + n]; }
        ASTD_g[a2 * 256 + e] = __float2half(w);
    }
}

// ---------------- persistent HMMA + TMA-ring LSTM ----------------
__global__ void __launch_bounds__(NT, 1) __cluster_dims__(2, 1, 1)
lstm_tc(const float* __restrict__ h0, const float* __restrict__ c0,
        const float* __restrict__ start, const float* __restrict__ b_out,
        float* __restrict__ out, int B, int steps) {
    extern __shared__ char smem[];
    const uint32_t sb = smem_u32(smem);
    const uint32_t bar0 = sb + SM_BAR;
    const int tid = threadIdx.x, wid = tid >> 5, lane = tid & 31;
    const uint32_t rank = ctarank(), peer = rank ^ 1u;
    const int r0 = blockIdx.x * 8;
    const int TOTAL = 38 + (steps - 1) * 19 + 19;

    if (tid == 0) {
        #pragma unroll
        for (int s = 0; s < NCHUNK; ++s) {
            mbar_init(bar0 + s * 16, 1);       // full: expect_tx
            mbar_init(bar0 + s * 16 + 8, 38);  // empty: 19 warps x 2 CTAs
        }
    }
    // zero B region, copy biases to SMEM
    for (int i = tid; i < 9728 / 4; i += NT) ((uint32_t*)(smem + SM_HX))[i] = 0;
    for (int i = tid; i < G4; i += NT) {
        ((float*)(smem + SM_BIAS))[i] = biasf_g[i];
        ((float*)(smem + SM_BIAS + 4800))[i] = bias2_g[i];
    }
    __syncthreads();
    // fill x0 (k 0-299) and h0 (k 304-603) as fp16
    for (int idx = tid; idx < HH * 8; idx += NT) {
        int u = idx >> 3, b = idx & 7;
        *(__half*)(smem + SM_HX + b * 1216 + u * 2) =
            __float2half(start[(size_t)(r0 + b) * HH + u]);
        *(__half*)(smem + SM_HX + b * 1216 + 608 + u * 2) =
            __float2half(h0[(size_t)(r0 + b) * HH + u]);
    }

    const int q = lane & 3, lr = lane >> 2;
    const bool owner = (lane & 15) < 4;
    const uint32_t lm_off = (uint32_t)((lane & 15) * 32 + (lane >> 4) * 16);
    const bool comp = (wid < 19);
    const bool isGateW = (wid < 15), isOutW = (wid >= 15 && wid < 19);

    // gate-warp owner state: c for 5 tiles x (2 units x 2 batch)
    float cst[5][4];
    int uAs[5];
    if (isGateW && owner) {
        #pragma unroll
        for (int i = 0; i < 5; ++i) {
            int T = wid * 5 + i;
            int uA = 4 * T + ((lane < 16) ? 0 : 1);
            uAs[i] = uA;
            #pragma unroll
            for (int c4 = 0; c4 < 4; ++c4) {
                int u = (c4 >> 1) ? (uA + 2) : uA;
                int ns = 2 * q + (c4 & 1);
                cst[i][c4] = c0[(size_t)(r0 + ns) * HH + u];
            }
        }
    }
    // out-warp biases
    float bo0[5], bo1[5];
    int n0s[5];
    if (isOutW) {
        #pragma unroll
        for (int i = 0; i < 5; ++i) {
            int T = wid * 5 + i;
            int n0 = 16 * (T - 75) + lr;
            n0s[i] = (T < 94) ? n0 : HH;
            bo0[i] = (T < 94 && n0 < HH) ? __ldg(&b_out[n0]) : 0.f;
            bo1[i] = (T < 94 && n0 + 8 < HH) ? __ldg(&b_out[n0 + 8]) : 0.f;
        }
    }
    __syncthreads();
    asm volatile("barrier.cluster.arrive.aligned;" ::: "memory");
    asm volatile("barrier.cluster.wait.aligned;" ::: "memory");

    // producer (thread 608)
    int p_slot = 0, p_phase = 1;
    auto produce = [&](int g) {
        mbar_wait_rlx(bar0 + p_slot * 16 + 8, (uint32_t)p_phase);
        const char* src; int bytes;
        if (g < 38) {
            src = (const char*)A0_g + (size_t)g * 38400; bytes = 38400;
        } else if (g < 38 + (steps - 1) * 19) {
            int j = (g - 38) % 19;
            src = (const char*)ASTD_g + (size_t)j * 48128; bytes = 48128;
        } else {
            int j = g - 38 - (steps - 1) * 19;
            src = (const char*)ASTD_g + (size_t)j * 48128 + 75 * 512; bytes = 9728;
        }
        int half_ = bytes >> 1;
        uint32_t full = bar0 + p_slot * 16;
        uint32_t dst = sb + SM_CHUNK + p_slot * CHUNK_MAX + rank * half_;
        mbar_expect_tx(full, (uint32_t)bytes);
        bulk_mc(dst, src + (size_t)rank * half_, (uint32_t)half_, full, 0x3);
        if (++p_slot == NCHUNK) { p_slot = 0; p_phase ^= 1; }
    };
    if (tid == 608) {
        #pragma unroll
        for (int i = 0; i < NCHUNK; ++i) produce(i);
    }

    int c_slot = 0, c_phase = 0, gi = 0;
    float acc[5][4];

    // consume one chunk; mode 0=step0(gates only), 1=steady(all), 2=tail(out only)
    auto consume = [&](int ktB, int mode) {
        if (comp) {
            mbar_wait_acq(bar0 + c_slot * 16, (uint32_t)c_phase);
            uint32_t cb = sb + SM_CHUNK + c_slot * CHUNK_MAX;
            uint32_t boff = (uint32_t)(lr * 1216 + ktB * 32 + q * 4);
            uint32_t b0 = *(const uint32_t*)(smem + boff);
            uint32_t b1 = *(const uint32_t*)(smem + boff + 16);
            #pragma unroll
            for (int i = 0; i < 5; ++i) {
                int t = wid * 5 + i;
                bool go = (mode == 0) ? (t < 75)
                        : (mode == 2) ? (t >= 75 && t < 94) : (t < 94);
                if (go) {
                    uint32_t off = (uint32_t)((mode == 2 ? t - 75 : t) * 512);
                    uint32_t a[4];
                    ldsm4(a, cb + off + lm_off);
                    mma16(acc[i], a, b0, b1);
                }
            }
            if (lane == 0) {
                mbar_arrive(bar0 + c_slot * 16 + 8);
                mbar_arrive_cluster(bar0 + c_slot * 16 + 8, peer);
            }
        }
        if (tid == 608 && gi + NCHUNK < TOTAL) produce(gi + NCHUNK);
        if (++c_slot == NCHUNK) { c_slot = 0; c_phase ^= 1; }
        ++gi;
    };
    auto reset_acc = [&]() {
        #pragma unroll
        for (int i = 0; i < 5; ++i)
            #pragma unroll
            for (int p = 0; p < 4; ++p) acc[i][p] = 0.f;
    };
    // gate epilogue: activations -> c,h; write h fp16 to SM_HX (h section)
    auto gate_epi = [&](bool step0) {
        #pragma unroll
        for (int i = 0; i < 5; ++i) {
            float fv[4], gv[4], ov[4];
            #pragma unroll
            for (int p = 0; p < 4; ++p) {
                fv[p] = __shfl_down_sync(0xffffffffu, acc[i][p], 4);
                gv[p] = __shfl_down_sync(0xffffffffu, acc[i][p], 8);
                ov[p] = __shfl_down_sync(0xffffffffu, acc[i][p], 12);
            }
            if (owner) {
                int uA = uAs[i];
                uint32_t bb = (uint32_t)SM_BIAS + (step0 ? 4800u : 0u);
                float4 bA = *(const float4*)(smem + bb + uA * 16);
                float4 bB = *(const float4*)(smem + bb + (uA + 2) * 16);
                #pragma unroll
                for (int c4 = 0; c4 < 4; ++c4) {
                    int ui = c4 >> 1, nn = c4 & 1;
                    int u = ui ? (uA + 2) : uA;
                    float4 bv = ui ? bB : bA;
                    float ii = sigf(acc[i][c4] + bv.x);
                    float ff = sigf(fv[c4] + bv.y);
                    float gg = tanhf_fast(gv[c4] + bv.z);
                    float oo = sigf(ov[c4] + bv.w);
                    float cc = fmaf(ff, cst[i][c4], ii * gg);
                    cst[i][c4] = cc;
                    float h = oo * tanhf_fast(cc);
                    int ns = 2 * q + nn;
                    *(__half*)(smem + ns * 1216 + 608 + u * 2) = __float2half(h);
                }
            }
        }
    };
    auto out_epi = [&](int tdst) {
        float* orow = out + ((size_t)tdst * B + r0) * HH;
        #pragma unroll
        for (int i = 0; i < 5; ++i) {
            int t = wid * 5 + i;
            if (t < 94) {
                int n0 = n0s[i], n1 = n0 + 8;
                if (n0 < HH) {
                    orow[(size_t)(2 * q) * HH + n0]     = acc[i][0] + bo0[i];
                    orow[(size_t)(2 * q + 1) * HH + n0] = acc[i][1] + bo0[i];
                }
                if (n1 < HH) {
                    orow[(size_t)(2 * q) * HH + n1]     = acc[i][2] + bo1[i];
                    orow[(size_t)(2 * q + 1) * HH + n1] = acc[i][3] + bo1[i];
                }
            }
        }
    };

    // ---- step 0: gates from (x0|h0), 38 k-slices ----
    reset_acc();
    for (int j = 0; j < 38; ++j) consume(j, 0);
    __syncthreads();
    if (isGateW) gate_epi(true);
    __syncthreads();

    // ---- steps 1..steps-1: out[s-1] + gates fused, 19 k-slices ----
    for (int s = 1; s < steps; ++s) {
        reset_acc();
        for (int j = 0; j < 19; ++j) consume(19 + j, 1);
        __syncthreads();
        if (isOutW) out_epi(s - 1);
        if (isGateW) gate_epi(false);
        __syncthreads();
    }

    // ---- tail: out[steps-1] from h_steps ----
    reset_acc();
    for (int j = 0; j < 19; ++j) consume(19 + j, 2);
    if (isOutW) out_epi(steps - 1);

    asm volatile("barrier.cluster.arrive.aligned;" ::: "memory");
    asm volatile("barrier.cluster.wait.aligned;" ::: "memory");
}

// ---------------- launch ----------------
extern "C" void kernel_launch(void* const* d_in, const int* in_sizes, int n_in,
                              void* d_out, int out_size) {
    const float* h0 = (const float*)d_in[0];
    const float* c0 = (const float*)d_in[1];
    const float* start = (const float*)d_in[2];
    const float* W_ih = (const float*)d_in[3];
    const float* W_hh = (const float*)d_in[4];
    const float* b_ih = (const float*)d_in[5];
    const float* b_hh = (const float*)d_in[6];
    const float* W_out = (const float*)d_in[7];
    const float* b_out = (const float*)d_in[8];
    int B = in_sizes[0] / HH;            // 1024
    int steps = out_size / (B * HH);     // 256

    int pe = 600 * G4 + HH * HH + G4;
    prep_basic<<<(pe + 255) / 256, 256>>>(W_ih, W_hh, b_ih, b_hh, W_out);
    dim3 fg(G4 / 16, HH / 20);
    prep_fold<<<fg, 320>>>(W_ih, W_hh, W_out);
    prep_biasf<<<(G4 + 255) / 256, 256>>>(W_ih, b_ih, b_hh, b_out);
    prep_pack<<<((2850 + 1786) * 256 + 255) / 256, 256>>>();

    cudaFuncSetAttribute(lstm_tc, cudaFuncAttributeMaxDynamicSharedMemorySize, SM_TOTAL);
    lstm_tc<<<B / 8, NT, SM_TOTAL>>>(h0, c0, start, b_out, (float*)d_out, B, steps);
}